// round 1
// baseline (speedup 1.0000x reference)
#include <cuda_runtime.h>
#include <cstdint>
#include <cstdio>

// ============================================================================
// Device scratch (static __device__ arrays; no runtime allocation allowed)
// ============================================================================
__device__ float g_wm1[3456];
__device__ float g_wm2[294912];
__device__ float g_wm3[1179648];
__device__ float g_fwm1[524288];
__device__ float g_fwm2[10240];

__device__ float g_h1[64u * 128u * 64u * 64u];   // conv1 out
__device__ float g_h2[64u * 256u * 32u * 32u];   // conv2 out
__device__ float g_h3[64u * 512u * 16u * 16u];   // conv3 out
__device__ float g_pool[64 * 512];
__device__ float g_a1[64 * 1024];

__device__ unsigned g_hist[65536];
struct Sel {
    unsigned b1, rank1, tbits, r, tieCount, idxThresh;
    unsigned tieIdx[2048];
};
__device__ Sel g_sel;

// ============================================================================
// Mask construction: exact selection of the j-th smallest |score| (bit-exact,
// with JAX stable-argsort tie semantics: among equal values, the ones with
// the SMALLEST flat index are dropped first).
// ============================================================================
__global__ void k_zero_hist() {
    int i = blockIdx.x * blockDim.x + threadIdx.x;
    if (i < 65536) g_hist[i] = 0;
}

__global__ void k_hist1(const float* __restrict__ s, int n) {
    for (int i = blockIdx.x * blockDim.x + threadIdx.x; i < n;
         i += gridDim.x * blockDim.x) {
        unsigned b = __float_as_uint(fabsf(s[i]));
        atomicAdd(&g_hist[b >> 16], 1u);
    }
}

__global__ void k_scan1(unsigned target) {
    __shared__ unsigned pre[1024];
    int tid = threadIdx.x;
    unsigned local = 0;
    for (int k = 0; k < 64; k++) local += g_hist[tid * 64 + k];
    pre[tid] = local;
    __syncthreads();
    if (tid == 0) {
        unsigned run = 0;
        for (int i = 0; i < 1024; i++) { unsigned v = pre[i]; pre[i] = run; run += v; }
    }
    __syncthreads();
    unsigned run = pre[tid];
    for (int k = 0; k < 64; k++) {
        unsigned h = g_hist[tid * 64 + k];
        if (h && run <= target && target < run + h) {
            g_sel.b1 = (unsigned)(tid * 64 + k);
            g_sel.rank1 = target - run;
        }
        run += h;
    }
}

__global__ void k_hist2(const float* __restrict__ s, int n) {
    unsigned b1 = g_sel.b1;
    for (int i = blockIdx.x * blockDim.x + threadIdx.x; i < n;
         i += gridDim.x * blockDim.x) {
        unsigned b = __float_as_uint(fabsf(s[i]));
        if ((b >> 16) == b1) atomicAdd(&g_hist[b & 0xFFFFu], 1u);
    }
}

__global__ void k_scan2() {
    __shared__ unsigned pre[1024];
    int tid = threadIdx.x;
    unsigned target = g_sel.rank1;
    unsigned local = 0;
    for (int k = 0; k < 64; k++) local += g_hist[tid * 64 + k];
    pre[tid] = local;
    __syncthreads();
    if (tid == 0) {
        unsigned run = 0;
        for (int i = 0; i < 1024; i++) { unsigned v = pre[i]; pre[i] = run; run += v; }
        g_sel.tieCount = 0;
    }
    __syncthreads();
    unsigned run = pre[tid];
    for (int k = 0; k < 64; k++) {
        unsigned h = g_hist[tid * 64 + k];
        if (h && run <= target && target < run + h) {
            g_sel.tbits = (g_sel.b1 << 16) | (unsigned)(tid * 64 + k);
            g_sel.r = target - run;
        }
        run += h;
    }
}

__global__ void k_ties(const float* __restrict__ s, int n) {
    unsigned t = g_sel.tbits;
    for (int i = blockIdx.x * blockDim.x + threadIdx.x; i < n;
         i += gridDim.x * blockDim.x) {
        unsigned b = __float_as_uint(fabsf(s[i]));
        if (b == t) {
            unsigned p = atomicAdd(&g_sel.tieCount, 1u);
            if (p < 2048) g_sel.tieIdx[p] = (unsigned)i;
        }
    }
}

__global__ void k_tiefin() {
    unsigned nt = g_sel.tieCount;
    if (nt > 2048) nt = 2048;
    // insertion sort (nt is almost always 1, rarely a handful)
    for (unsigned i = 1; i < nt; i++) {
        unsigned v = g_sel.tieIdx[i];
        int j = (int)i;
        while (j > 0 && g_sel.tieIdx[j - 1] > v) { g_sel.tieIdx[j] = g_sel.tieIdx[j - 1]; j--; }
        g_sel.tieIdx[j] = v;
    }
    unsigned r = g_sel.r;
    if (nt == 0) { g_sel.idxThresh = 0; return; }
    if (r >= nt) r = nt - 1;
    g_sel.idxThresh = g_sel.tieIdx[r];
}

__global__ void k_apply(const float* __restrict__ s, const float* __restrict__ w,
                        float* __restrict__ wm, int n) {
    unsigned t = g_sel.tbits;
    unsigned it = g_sel.idxThresh;
    for (int i = blockIdx.x * blockDim.x + threadIdx.x; i < n;
         i += gridDim.x * blockDim.x) {
        unsigned b = __float_as_uint(fabsf(s[i]));
        bool keep = (b > t) || (b == t && (unsigned)i >= it);
        wm[i] = keep ? w[i] : 0.0f;
    }
}

// ============================================================================
// Direct 3x3 conv + bias + ReLU.
// Block = 128 threads, tile = 8x8 output pixels x 128 output channels.
// Thread micro-tile = 8 px (one row) x 8 co -> 64 accumulators.
// Input channels chunked by CC through shared memory.
// ============================================================================
template <int CIN, int CC, int S, int HIN, int WIN, int HOUT, int WOUT, int COUT>
__global__ __launch_bounds__(128) void k_conv3x3(
    const float* __restrict__ in, const float* __restrict__ w,
    const float* __restrict__ bias, float* __restrict__ out) {
    constexpr int R = 7 * S + 3;  // input patch span for 8 outputs
    __shared__ float s_in[CC][R][R];
    __shared__ float s_w[CC * 9][128];

    const int n = blockIdx.z;
    const int co0 = blockIdx.y * 128;
    constexpr int TX = WOUT / 8;
    const int tx0 = (blockIdx.x % TX) * 8;
    const int ty0 = (blockIdx.x / TX) * 8;
    const int tid = threadIdx.x;
    const int cog = tid >> 3;  // 0..15 -> 8 consecutive channels each
    const int pxg = tid & 7;   // output row within tile

    float acc[8][8];  // [c][x]
#pragma unroll
    for (int c = 0; c < 8; c++)
#pragma unroll
        for (int x = 0; x < 8; x++) acc[c][x] = 0.0f;

    const int base_y = ty0 * S - 1;
    const int base_x = tx0 * S - 1;

    for (int c0 = 0; c0 < CIN; c0 += CC) {
        // weights: thread tid owns output channel (co0 + tid)
        {
            const float* wp = w + (size_t)(co0 + tid) * (CIN * 9) + (size_t)c0 * 9;
#pragma unroll
            for (int q = 0; q < CC * 9; q++) s_w[q][tid] = wp[q];
        }
        // input patch
        for (int idx = tid; idx < CC * R * R; idx += 128) {
            int cc = idx / (R * R);
            int rem = idx - cc * R * R;
            int yy = rem / R;
            int xx = rem - yy * R;
            int iy = base_y + yy, ix = base_x + xx;
            float v = 0.0f;
            if (iy >= 0 && iy < HIN && ix >= 0 && ix < WIN)
                v = in[(((size_t)n * CIN + c0 + cc) * HIN + iy) * WIN + ix];
            s_in[cc][yy][xx] = v;
        }
        __syncthreads();

        for (int cc = 0; cc < CC; ++cc) {
#pragma unroll
            for (int ky = 0; ky < 3; ++ky) {
                const float* inrow = &s_in[cc][pxg * S + ky][0];
#pragma unroll
                for (int kx = 0; kx < 3; ++kx) {
                    const float* wrow = &s_w[cc * 9 + ky * 3 + kx][cog * 8];
                    float vv[8];
#pragma unroll
                    for (int x = 0; x < 8; x++) vv[x] = inrow[x * S + kx];
#pragma unroll
                    for (int c = 0; c < 8; c++) {
                        float wc = wrow[c];
#pragma unroll
                        for (int x = 0; x < 8; x++)
                            acc[c][x] = fmaf(vv[x], wc, acc[c][x]);
                    }
                }
            }
        }
        __syncthreads();
    }

#pragma unroll
    for (int c = 0; c < 8; c++) {
        int co = co0 + cog * 8 + c;
        float bv = bias[co];
#pragma unroll
        for (int x = 0; x < 8; x++) {
            float v = acc[c][x] + bv;
            out[(((size_t)n * COUT + co) * HOUT + (ty0 + pxg)) * WOUT + (tx0 + x)] =
                v > 0.0f ? v : 0.0f;
        }
    }
}

// ============================================================================
// Global average pool 16x16 -> scalar. grid (512, 64), block 256.
// ============================================================================
__global__ void k_gap(const float* __restrict__ h, float* __restrict__ pool) {
    int c = blockIdx.x, n = blockIdx.y;
    const float* p = h + ((size_t)n * 512 + c) * 256;
    float v = p[threadIdx.x];
#pragma unroll
    for (int off = 16; off > 0; off >>= 1)
        v += __shfl_down_sync(0xffffffffu, v, off);
    __shared__ float red[8];
    int lane = threadIdx.x & 31, wid = threadIdx.x >> 5;
    if (lane == 0) red[wid] = v;
    __syncthreads();
    if (threadIdx.x == 0) {
        float s = 0.0f;
        for (int i = 0; i < 8; i++) s += red[i];
        pool[n * 512 + c] = s * (1.0f / 256.0f);
    }
}

// ============================================================================
// FC1: [64,512] x [1024,512]^T + b, ReLU. grid (4, 64), block 256.
// ============================================================================
__global__ void k_fc1(const float* __restrict__ pool, const float* __restrict__ w,
                      const float* __restrict__ b, float* __restrict__ out) {
    int n = blockIdx.y;
    int o = blockIdx.x * 256 + threadIdx.x;
    __shared__ float sp[512];
    for (int k = threadIdx.x; k < 512; k += 256) sp[k] = pool[n * 512 + k];
    __syncthreads();
    float acc = 0.0f;
    const float* wp = w + (size_t)o * 512;
#pragma unroll 8
    for (int k = 0; k < 512; k++) acc = fmaf(sp[k], wp[k], acc);
    float v = acc + b[o];
    out[n * 1024 + o] = v > 0.0f ? v : 0.0f;
}

// ============================================================================
// FC2: [64,1024] x [10,1024]^T + b. grid 64, block 320 (warp per output).
// ============================================================================
__global__ void k_fc2(const float* __restrict__ a, const float* __restrict__ w,
                      const float* __restrict__ b, float* __restrict__ out) {
    int n = blockIdx.x;
    int o = threadIdx.x >> 5, lane = threadIdx.x & 31;
    float acc = 0.0f;
    const float* ap = a + (size_t)n * 1024;
    const float* wp = w + (size_t)o * 1024;
    for (int k = lane; k < 1024; k += 32) acc = fmaf(ap[k], wp[k], acc);
#pragma unroll
    for (int off = 16; off > 0; off >>= 1)
        acc += __shfl_down_sync(0xffffffffu, acc, off);
    if (lane == 0) out[n * 10 + o] = acc + b[o];
}

// ============================================================================
// Host side
// ============================================================================
static void build_mask(const float* s, const float* w, float* wm, int n, unsigned j) {
    int blocks = (n + 255) / 256;
    if (blocks > 1184) blocks = 1184;
    k_zero_hist<<<256, 256>>>();
    k_hist1<<<blocks, 256>>>(s, n);
    k_scan1<<<1, 1024>>>(j);
    k_zero_hist<<<256, 256>>>();
    k_hist2<<<blocks, 256>>>(s, n);
    k_scan2<<<1, 1024>>>();
    k_ties<<<blocks, 256>>>(s, n);
    k_tiefin<<<1, 1>>>();
    k_apply<<<blocks, 256>>>(s, w, wm, n);
}

extern "C" void kernel_launch(void* const* d_in, const int* in_sizes, int n_in,
                              void* d_out, int out_size) {
    (void)in_sizes; (void)n_in; (void)out_size;
    const float* x   = (const float*)d_in[0];
    const float* w1  = (const float*)d_in[1];
    const float* s1  = (const float*)d_in[2];
    const float* b1  = (const float*)d_in[3];
    const float* w2  = (const float*)d_in[4];
    const float* s2  = (const float*)d_in[5];
    const float* b2  = (const float*)d_in[6];
    const float* w3  = (const float*)d_in[7];
    const float* s3  = (const float*)d_in[8];
    const float* b3  = (const float*)d_in[9];
    const float* fw1 = (const float*)d_in[10];
    const float* fs1 = (const float*)d_in[11];
    const float* fb1 = (const float*)d_in[12];
    const float* fw2 = (const float*)d_in[13];
    const float* fs2 = (const float*)d_in[14];
    const float* fb2 = (const float*)d_in[15];
    float* out = (float*)d_out;

    float *wm1, *wm2, *wm3, *fwm1, *fwm2, *h1, *h2, *h3, *pool, *a1;
    cudaGetSymbolAddress((void**)&wm1, g_wm1);
    cudaGetSymbolAddress((void**)&wm2, g_wm2);
    cudaGetSymbolAddress((void**)&wm3, g_wm3);
    cudaGetSymbolAddress((void**)&fwm1, g_fwm1);
    cudaGetSymbolAddress((void**)&fwm2, g_fwm2);
    cudaGetSymbolAddress((void**)&h1, g_h1);
    cudaGetSymbolAddress((void**)&h2, g_h2);
    cudaGetSymbolAddress((void**)&h3, g_h3);
    cudaGetSymbolAddress((void**)&pool, g_pool);
    cudaGetSymbolAddress((void**)&a1, g_a1);

    // Masked weights (exact top-50% by |score| with stable-argsort tie-break)
    build_mask(s1,  w1,  wm1,  3456,    1728u);
    build_mask(s2,  w2,  wm2,  294912,  147456u);
    build_mask(s3,  w3,  wm3,  1179648, 589824u);
    build_mask(fs1, fw1, fwm1, 524288,  262144u);
    build_mask(fs2, fw2, fwm2, 10240,   5120u);

    // conv1: [64,3,64,64] -> [64,128,64,64], stride 1
    k_conv3x3<3, 3, 1, 64, 64, 64, 64, 128>
        <<<dim3(64, 1, 64), 128>>>(x, wm1, b1, h1);
    // conv2: -> [64,256,32,32], stride 2
    k_conv3x3<128, 8, 2, 64, 64, 32, 32, 256>
        <<<dim3(16, 2, 64), 128>>>(h1, wm2, b2, h2);
    // conv3: -> [64,512,16,16], stride 2
    k_conv3x3<256, 8, 2, 32, 32, 16, 16, 512>
        <<<dim3(4, 4, 64), 128>>>(h2, wm3, b3, h3);

    k_gap<<<dim3(512, 64), 256>>>(h3, pool);
    k_fc1<<<dim3(4, 64), 256>>>(pool, fwm1, fb1, a1);
    k_fc2<<<64, 320>>>(a1, fwm2, fb2, out);
}